// round 1
// baseline (speedup 1.0000x reference)
#include <cuda_runtime.h>

#define Bz 8
#define Tz 2048
#define Dz 1024
#define Kz 1024
#define BT (Bz*Tz)

// ---------------- scratch (device globals; no allocations allowed) ----------
__device__ float g_xr[BT*Dz];
__device__ float g_xk[BT*Dz];
__device__ float g_xv[BT*Dz];
__device__ float g_r [BT*Dz];
__device__ float g_k [BT*Dz];
__device__ float g_v [BT*Dz];
__device__ float g_att[BT*Dz];
__device__ float g_stats[2*Bz];
__device__ float g_mean[Bz];
__device__ float g_rstd[Bz];

// ---------------- small helpers ---------------------------------------------
__global__ void zero_stats_kernel() {
    int i = threadIdx.x;
    if (i < 2*Bz) g_stats[i] = 0.f;
}

// ---------------- token shift + time-mix ------------------------------------
// xr/xk/xv = x*mix + x_prev*(1-mix); x_prev[t=0] comes from state[...,2]
__global__ void mix_kernel(const float* __restrict__ x,
                           const float* __restrict__ state,
                           const float* __restrict__ tmr,
                           const float* __restrict__ tmk,
                           const float* __restrict__ tmv)
{
    int idx = blockIdx.x * blockDim.x + threadIdx.x;
    long e = (long)idx * 4;
    if (e >= (long)BT*Dz) return;
    int d  = (int)(e & (Dz-1));
    int bt = (int)(e >> 10);
    int t  = bt & (Tz-1);
    int b  = bt >> 11;

    float4 xc = *(const float4*)(x + e);
    float4 xp;
    if (t == 0) {
        // state layout (B,H=1,K,3): ((b*K + d)*3 + comp)
        xp.x = state[(b*Kz + d + 0)*3 + 2];
        xp.y = state[(b*Kz + d + 1)*3 + 2];
        xp.z = state[(b*Kz + d + 2)*3 + 2];
        xp.w = state[(b*Kz + d + 3)*3 + 2];
    } else {
        xp = *(const float4*)(x + e - Dz);
    }
    float4 mr = *(const float4*)(tmr + d);
    float4 mk = *(const float4*)(tmk + d);
    float4 mv = *(const float4*)(tmv + d);

    float4 o;
    o.x = xc.x*mr.x + xp.x*(1.f-mr.x);
    o.y = xc.y*mr.y + xp.y*(1.f-mr.y);
    o.z = xc.z*mr.z + xp.z*(1.f-mr.z);
    o.w = xc.w*mr.w + xp.w*(1.f-mr.w);
    *(float4*)(g_xr + e) = o;

    o.x = xc.x*mk.x + xp.x*(1.f-mk.x);
    o.y = xc.y*mk.y + xp.y*(1.f-mk.y);
    o.z = xc.z*mk.z + xp.z*(1.f-mk.z);
    o.w = xc.w*mk.w + xp.w*(1.f-mk.w);
    *(float4*)(g_xk + e) = o;

    o.x = xc.x*mv.x + xp.x*(1.f-mv.x);
    o.y = xc.y*mv.y + xp.y*(1.f-mv.y);
    o.z = xc.z*mv.z + xp.z*(1.f-mv.z);
    o.w = xc.w*mv.w + xp.w*(1.f-mv.w);
    *(float4*)(g_xv + e) = o;
}

// ---------------- SGEMM: C[M,N] = A[M,K] * W[N,K]^T --------------------------
// MODE 0: plain store. MODE 1: sigmoid epilogue (r path).
// MODE 2: A is normalized on load: (a - mean[b])*rstd[b]*gamma[d] + beta[d].
// Tiles: 128x128x8, 256 threads, 8x8 per-thread micro-tile.
#define GBM 128
#define GBN 128
#define GBK 8

template<int MODE>
__global__ __launch_bounds__(256, 2)
void gemm_kernel(const float* __restrict__ A, const float* __restrict__ W,
                 float* __restrict__ C,
                 const float* __restrict__ gamma, const float* __restrict__ beta)
{
    __shared__ float As[GBK][GBM+4];
    __shared__ float Bs[GBK][GBN+4];
    const int Kd = Dz;

    int tid = threadIdx.x;
    int bm = blockIdx.y * GBM;
    int bn = blockIdx.x * GBN;
    int tx = tid & 15, ty = tid >> 4;
    int lrow = tid >> 1;
    int lcol = (tid & 1) * 4;

    float m_mean = 0.f, m_rstd = 1.f;
    if (MODE == 2) {
        int bb = bm / Tz;         // whole 128-row tile lies inside one batch
        m_mean = g_mean[bb];
        m_rstd = g_rstd[bb];
    }

    float acc[8][8];
    #pragma unroll
    for (int i = 0; i < 8; i++)
        #pragma unroll
        for (int j = 0; j < 8; j++) acc[i][j] = 0.f;

    const float* Aptr = A + (size_t)(bm + lrow)*Kd + lcol;
    const float* Wptr = W + (size_t)(bn + lrow)*Kd + lcol;

    for (int k0 = 0; k0 < Kd; k0 += GBK) {
        float4 av = *(const float4*)(Aptr + k0);
        float4 wv = *(const float4*)(Wptr + k0);
        if (MODE == 2) {
            float4 gv = *(const float4*)(gamma + k0 + lcol);
            float4 bv = *(const float4*)(beta  + k0 + lcol);
            av.x = (av.x - m_mean)*m_rstd*gv.x + bv.x;
            av.y = (av.y - m_mean)*m_rstd*gv.y + bv.y;
            av.z = (av.z - m_mean)*m_rstd*gv.z + bv.z;
            av.w = (av.w - m_mean)*m_rstd*gv.w + bv.w;
        }
        As[lcol+0][lrow] = av.x;
        As[lcol+1][lrow] = av.y;
        As[lcol+2][lrow] = av.z;
        As[lcol+3][lrow] = av.w;
        Bs[lcol+0][lrow] = wv.x;
        Bs[lcol+1][lrow] = wv.y;
        Bs[lcol+2][lrow] = wv.z;
        Bs[lcol+3][lrow] = wv.w;
        __syncthreads();

        #pragma unroll
        for (int kk = 0; kk < GBK; kk++) {
            float ar[8], br[8];
            *(float4*)&ar[0] = *(const float4*)&As[kk][ty*8];
            *(float4*)&ar[4] = *(const float4*)&As[kk][ty*8+4];
            *(float4*)&br[0] = *(const float4*)&Bs[kk][tx*8];
            *(float4*)&br[4] = *(const float4*)&Bs[kk][tx*8+4];
            #pragma unroll
            for (int i = 0; i < 8; i++)
                #pragma unroll
                for (int j = 0; j < 8; j++)
                    acc[i][j] = fmaf(ar[i], br[j], acc[i][j]);
        }
        __syncthreads();
    }

    #pragma unroll
    for (int i = 0; i < 8; i++) {
        float* cp = C + (size_t)(bm + ty*8 + i)*Dz + bn + tx*8;
        float v[8];
        #pragma unroll
        for (int j = 0; j < 8; j++) {
            float z = acc[i][j];
            if (MODE == 1) z = 1.f / (1.f + __expf(-z));
            v[j] = z;
        }
        *(float4*)cp       = make_float4(v[0], v[1], v[2], v[3]);
        *(float4*)(cp + 4) = make_float4(v[4], v[5], v[6], v[7]);
    }
}

// ---------------- WKV sequential scan + att = r*wkv + GN partial stats -------
__global__ void wkv_kernel(const float* __restrict__ state,
                           const float* __restrict__ tdecay,
                           const float* __restrict__ tfirst)
{
    int b = blockIdx.y;
    int c = blockIdx.x * blockDim.x + threadIdx.x;   // channel 0..1023

    float w  = expf(-expf(tdecay[c]));   // full precision once per thread
    float eu = expf(tfirst[c]);
    float num = state[(b*Kz + c)*3 + 0];
    float den = state[(b*Kz + c)*3 + 1];

    const float* kp = g_k   + (size_t)b*Tz*Dz + c;
    const float* vp = g_v   + (size_t)b*Tz*Dz + c;
    const float* rp = g_r   + (size_t)b*Tz*Dz + c;
    float*       op = g_att + (size_t)b*Tz*Dz + c;

    float s1 = 0.f, s2 = 0.f;
    #pragma unroll 4
    for (int t = 0; t < Tz; t++) {
        float kk = kp[(size_t)t*Dz];
        float vv = vp[(size_t)t*Dz];
        float rr = rp[(size_t)t*Dz];
        float ek = __expf(kk);
        float bonus = eu * ek;
        float wkv = __fdividef(fmaf(bonus, vv, num), den + bonus + 1e-9f);
        float att = rr * wkv;
        op[(size_t)t*Dz] = att;
        s1 += att;
        s2 = fmaf(att, att, s2);
        num = fmaf(ek, vv, num * w);
        den = fmaf(den, w, ek);
    }

    __shared__ float sh1[256], sh2[256];
    int tid = threadIdx.x;
    sh1[tid] = s1; sh2[tid] = s2;
    __syncthreads();
    for (int s = 128; s > 0; s >>= 1) {
        if (tid < s) { sh1[tid] += sh1[tid+s]; sh2[tid] += sh2[tid+s]; }
        __syncthreads();
    }
    if (tid == 0) {
        atomicAdd(&g_stats[2*b+0], sh1[0]);
        atomicAdd(&g_stats[2*b+1], sh2[0]);
    }
}

__global__ void finalize_kernel() {
    int b = threadIdx.x;
    if (b < Bz) {
        float n = (float)Tz * (float)Dz;
        float mean = g_stats[2*b] / n;
        float var  = g_stats[2*b+1] / n - mean*mean;
        g_mean[b] = mean;
        g_rstd[b] = rsqrtf(var + 1e-5f);
    }
}

// ---------------- launcher ---------------------------------------------------
extern "C" void kernel_launch(void* const* d_in, const int* in_sizes, int n_in,
                              void* d_out, int out_size)
{
    const float* x      = (const float*)d_in[0];
    const float* state  = (const float*)d_in[1];
    const float* W_r    = (const float*)d_in[2];
    const float* W_k    = (const float*)d_in[3];
    const float* W_v    = (const float*)d_in[4];
    const float* W_o    = (const float*)d_in[5];
    const float* tmr    = (const float*)d_in[6];
    const float* tmk    = (const float*)d_in[7];
    const float* tmv    = (const float*)d_in[8];
    const float* tdecay = (const float*)d_in[9];
    const float* tfirst = (const float*)d_in[10];
    const float* gamma  = (const float*)d_in[11];
    const float* beta   = (const float*)d_in[12];
    float* out = (float*)d_out;

    // device pointers for scratch globals (query only; no allocation)
    float *p_xr, *p_xk, *p_xv, *p_r, *p_k, *p_v, *p_att;
    cudaGetSymbolAddress((void**)&p_xr,  g_xr);
    cudaGetSymbolAddress((void**)&p_xk,  g_xk);
    cudaGetSymbolAddress((void**)&p_xv,  g_xv);
    cudaGetSymbolAddress((void**)&p_r,   g_r);
    cudaGetSymbolAddress((void**)&p_k,   g_k);
    cudaGetSymbolAddress((void**)&p_v,   g_v);
    cudaGetSymbolAddress((void**)&p_att, g_att);

    zero_stats_kernel<<<1, 32>>>();

    mix_kernel<<<(BT*Dz/4 + 255)/256, 256>>>(x, state, tmr, tmk, tmv);

    dim3 ggrid(Dz/GBN, BT/GBM);   // (8, 128)
    gemm_kernel<1><<<ggrid, 256>>>(p_xr, W_r, p_r, nullptr, nullptr);
    gemm_kernel<0><<<ggrid, 256>>>(p_xk, W_k, p_k, nullptr, nullptr);
    gemm_kernel<0><<<ggrid, 256>>>(p_xv, W_v, p_v, nullptr, nullptr);

    wkv_kernel<<<dim3(Kz/256, Bz), 256>>>(state, tdecay, tfirst);
    finalize_kernel<<<1, 32>>>();

    gemm_kernel<2><<<ggrid, 256>>>(p_att, W_o, out, gamma, beta);
}

// round 3
// speedup vs baseline: 3.2806x; 3.2806x over previous
#include <cuda_runtime.h>
#include <cstdint>

#define Bz 8
#define Tz 2048
#define Dz 1024
#define Kz 1024
#define BT (Bz*Tz)

// ---------------- scratch (device globals; no allocations allowed) ----------
__device__ float g_xr[BT*Dz];
__device__ float g_xk[BT*Dz];
__device__ float g_xv[BT*Dz];
__device__ float g_r [BT*Dz];
__device__ float g_k [BT*Dz];
__device__ float g_v [BT*Dz];
__device__ float g_att[BT*Dz];
__device__ float g_W[4][Dz*Dz];          // tf32-rounded copies of W_r,W_k,W_v,W_o
__device__ float g_stats[2*Bz];
__device__ float g_mean[Bz];
__device__ float g_rstd[Bz];

// ---------------- helpers ----------------------------------------------------
__device__ __forceinline__ float rtf(float x) {          // round-to-nearest tf32
    uint32_t r;
    asm("cvt.rna.tf32.f32 %0, %1;" : "=r"(r) : "f"(x));
    return __uint_as_float(r);
}
__device__ __forceinline__ void cp16(uint32_t saddr, const void* g) {
    asm volatile("cp.async.cg.shared.global [%0], [%1], 16;" :: "r"(saddr), "l"(g) : "memory");
}
#define CP_COMMIT() asm volatile("cp.async.commit_group;" ::: "memory")
#define CP_WAIT1()  asm volatile("cp.async.wait_group 1;" ::: "memory")
#define CP_WAIT0()  asm volatile("cp.async.wait_group 0;" ::: "memory")

__device__ __forceinline__ uint32_t smem_u32(const void* p) {
    uint32_t a;
    asm("{ .reg .u64 t; cvta.to.shared.u64 t, %1; cvt.u32.u64 %0, t; }" : "=r"(a) : "l"(p));
    return a;
}
__device__ __forceinline__ void mma_tf32(float* d, const uint32_t* a, const uint32_t* b) {
    asm volatile(
        "mma.sync.aligned.m16n8k8.row.col.f32.tf32.tf32.f32 "
        "{%0,%1,%2,%3}, {%4,%5,%6,%7}, {%8,%9}, {%0,%1,%2,%3};"
        : "+f"(d[0]), "+f"(d[1]), "+f"(d[2]), "+f"(d[3])
        : "r"(a[0]), "r"(a[1]), "r"(a[2]), "r"(a[3]), "r"(b[0]), "r"(b[1]));
}

// ---------------- small kernels ----------------------------------------------
__global__ void zero_stats_kernel() {
    int i = threadIdx.x;
    if (i < 2*Bz) g_stats[i] = 0.f;
}

// tf32-round the 4 weight matrices into scratch
__global__ void round_w_kernel(const float* __restrict__ w0, const float* __restrict__ w1,
                               const float* __restrict__ w2, const float* __restrict__ w3)
{
    int m = blockIdx.y;
    const float* s = (m == 0) ? w0 : (m == 1) ? w1 : (m == 2) ? w2 : w3;
    long e = ((long)blockIdx.x * blockDim.x + threadIdx.x) * 4;
    if (e >= (long)Dz*Dz) return;
    float4 v = *(const float4*)(s + e);
    v.x = rtf(v.x); v.y = rtf(v.y); v.z = rtf(v.z); v.w = rtf(v.w);
    *(float4*)(&g_W[m][0] + e) = v;
}

// token shift + time-mix, outputs tf32-rounded
__global__ void mix_kernel(const float* __restrict__ x,
                           const float* __restrict__ state,
                           const float* __restrict__ tmr,
                           const float* __restrict__ tmk,
                           const float* __restrict__ tmv)
{
    int idx = blockIdx.x * blockDim.x + threadIdx.x;
    long e = (long)idx * 4;
    if (e >= (long)BT*Dz) return;
    int d  = (int)(e & (Dz-1));
    int bt = (int)(e >> 10);
    int t  = bt & (Tz-1);
    int b  = bt >> 11;

    float4 xc = *(const float4*)(x + e);
    float4 xp;
    if (t == 0) {
        xp.x = state[(b*Kz + d + 0)*3 + 2];
        xp.y = state[(b*Kz + d + 1)*3 + 2];
        xp.z = state[(b*Kz + d + 2)*3 + 2];
        xp.w = state[(b*Kz + d + 3)*3 + 2];
    } else {
        xp = *(const float4*)(x + e - Dz);
    }
    float4 mr = *(const float4*)(tmr + d);
    float4 mk = *(const float4*)(tmk + d);
    float4 mv = *(const float4*)(tmv + d);

    float4 o;
    o.x = rtf(xc.x*mr.x + xp.x*(1.f-mr.x));
    o.y = rtf(xc.y*mr.y + xp.y*(1.f-mr.y));
    o.z = rtf(xc.z*mr.z + xp.z*(1.f-mr.z));
    o.w = rtf(xc.w*mr.w + xp.w*(1.f-mr.w));
    *(float4*)(g_xr + e) = o;

    o.x = rtf(xc.x*mk.x + xp.x*(1.f-mk.x));
    o.y = rtf(xc.y*mk.y + xp.y*(1.f-mk.y));
    o.z = rtf(xc.z*mk.z + xp.z*(1.f-mk.z));
    o.w = rtf(xc.w*mk.w + xp.w*(1.f-mk.w));
    *(float4*)(g_xk + e) = o;

    o.x = rtf(xc.x*mv.x + xp.x*(1.f-mv.x));
    o.y = rtf(xc.y*mv.y + xp.y*(1.f-mv.y));
    o.z = rtf(xc.z*mv.z + xp.z*(1.f-mv.z));
    o.w = rtf(xc.w*mv.w + xp.w*(1.f-mv.w));
    *(float4*)(g_xv + e) = o;
}

// ---------------- TF32 mma.sync GEMM: C[M,N] = A[M,K] * W[N,K]^T -------------
// CTA tile 128x128, BK=32, 3-stage cp.async pipeline, 8 warps (2x4),
// warp tile 64x32, mma m16n8k8. MODE 0: plain store. MODE 1: sigmoid.
#define BKg 32
#define STRIDEW 36                      // padded words per 32-float row
#define STG_WORDS (128*STRIDEW)         // one operand stage: 4608 words
#define NSTAGE 3
#define GSMEM (NSTAGE*2*STG_WORDS*4)    // 110592 bytes
#define NCHUNK (Dz/BKg)                 // 32

template<int MODE>
__global__ void __launch_bounds__(256)
gemm_mma(const float* __restrict__ A, const float* __restrict__ W, float* __restrict__ C)
{
    extern __shared__ float smf[];
    const int tid  = threadIdx.x;
    const int wid  = tid >> 5;
    const int lane = tid & 31;
    const int gp   = lane >> 2;     // groupID
    const int tg   = lane & 3;      // thread-in-group
    const int wm   = (wid >> 2) * 64;
    const int wn   = (wid & 3) * 32;
    const int bm   = blockIdx.y * 128;
    const int bn   = blockIdx.x * 128;

    const float* Ag = A + (size_t)bm * Dz;
    const float* Wg = W + (size_t)bn * Dz;
    const uint32_t smb = smem_u32(smf);

    const int lrow = tid >> 3;   // 0..31
    const int lseg = tid & 7;    // 0..7 (16B segments)

    auto issue = [&](int it) {
        int s = it % NSTAGE;
        uint32_t stA = smb + (uint32_t)s * 2 * STG_WORDS * 4;
        uint32_t stB = stA + STG_WORDS * 4;
        int k0 = it * BKg;
        #pragma unroll
        for (int i = 0; i < 4; i++) {
            int r = lrow + 32 * i;
            uint32_t off = (uint32_t)(r * STRIDEW + lseg * 4) * 4;
            cp16(stA + off, Ag + (size_t)r * Dz + k0 + lseg * 4);
            cp16(stB + off, Wg + (size_t)r * Dz + k0 + lseg * 4);
        }
        CP_COMMIT();
    };

    float acc[4][4][4];
    #pragma unroll
    for (int mi = 0; mi < 4; mi++)
        #pragma unroll
        for (int ni = 0; ni < 4; ni++)
            #pragma unroll
            for (int q = 0; q < 4; q++) acc[mi][ni][q] = 0.f;

    issue(0);
    issue(1);

    #pragma unroll 1
    for (int it = 0; it < NCHUNK; it++) {
        int s = it % NSTAGE;
        CP_WAIT1();
        __syncthreads();
        if (it + 2 < NCHUNK) issue(it + 2);

        const float* stA = smf + s * 2 * STG_WORDS;
        const float* stB = stA + STG_WORDS;

        #pragma unroll
        for (int ks = 0; ks < 4; ks++) {
            uint32_t a[4][4], b[4][2];
            const int c = ks * 8 + tg;
            #pragma unroll
            for (int mi = 0; mi < 4; mi++) {
                int r = wm + mi * 16 + gp;
                a[mi][0] = __float_as_uint(stA[r * STRIDEW + c]);
                a[mi][1] = __float_as_uint(stA[(r + 8) * STRIDEW + c]);
                a[mi][2] = __float_as_uint(stA[r * STRIDEW + c + 4]);
                a[mi][3] = __float_as_uint(stA[(r + 8) * STRIDEW + c + 4]);
            }
            #pragma unroll
            for (int ni = 0; ni < 4; ni++) {
                int n = wn + ni * 8 + gp;
                b[ni][0] = __float_as_uint(stB[n * STRIDEW + c]);
                b[ni][1] = __float_as_uint(stB[n * STRIDEW + c + 4]);
            }
            #pragma unroll
            for (int mi = 0; mi < 4; mi++)
                #pragma unroll
                for (int ni = 0; ni < 4; ni++)
                    mma_tf32(acc[mi][ni], a[mi], b[ni]);
        }
    }
    CP_WAIT0();

    // epilogue
    #pragma unroll
    for (int mi = 0; mi < 4; mi++) {
        int r0 = bm + wm + mi * 16 + gp;
        #pragma unroll
        for (int ni = 0; ni < 4; ni++) {
            int cc = bn + wn + ni * 8 + tg * 2;
            float v0 = acc[mi][ni][0], v1 = acc[mi][ni][1];
            float v2 = acc[mi][ni][2], v3 = acc[mi][ni][3];
            if (MODE == 1) {
                v0 = 1.f/(1.f+__expf(-v0));
                v1 = 1.f/(1.f+__expf(-v1));
                v2 = 1.f/(1.f+__expf(-v2));
                v3 = 1.f/(1.f+__expf(-v3));
            }
            *(float2*)(C + (size_t)r0 * Dz + cc)       = make_float2(v0, v1);
            *(float2*)(C + (size_t)(r0 + 8) * Dz + cc) = make_float2(v2, v3);
        }
    }
}

// ---------------- WKV sequential scan + att = r*wkv + GN partial stats -------
__global__ void wkv_kernel(const float* __restrict__ state,
                           const float* __restrict__ tdecay,
                           const float* __restrict__ tfirst)
{
    int b = blockIdx.y;
    int c = blockIdx.x * blockDim.x + threadIdx.x;

    float w  = expf(-expf(tdecay[c]));
    float eu = expf(tfirst[c]);
    float num = state[(b*Kz + c)*3 + 0];
    float den = state[(b*Kz + c)*3 + 1];

    const float* kp = g_k   + (size_t)b*Tz*Dz + c;
    const float* vp = g_v   + (size_t)b*Tz*Dz + c;
    const float* rp = g_r   + (size_t)b*Tz*Dz + c;
    float*       op = g_att + (size_t)b*Tz*Dz + c;

    float s1 = 0.f, s2 = 0.f;
    #pragma unroll 4
    for (int t = 0; t < Tz; t++) {
        float kk = kp[(size_t)t*Dz];
        float vv = vp[(size_t)t*Dz];
        float rr = rp[(size_t)t*Dz];
        float ek = __expf(kk);
        float bonus = eu * ek;
        float wkv = __fdividef(fmaf(bonus, vv, num), den + bonus + 1e-9f);
        float att = rr * wkv;
        op[(size_t)t*Dz] = att;
        s1 += att;
        s2 = fmaf(att, att, s2);
        num = fmaf(ek, vv, num * w);
        den = fmaf(den, w, ek);
    }

    __shared__ float sh1[256], sh2[256];
    int tid = threadIdx.x;
    sh1[tid] = s1; sh2[tid] = s2;
    __syncthreads();
    for (int s = 128; s > 0; s >>= 1) {
        if (tid < s) { sh1[tid] += sh1[tid+s]; sh2[tid] += sh2[tid+s]; }
        __syncthreads();
    }
    if (tid == 0) {
        atomicAdd(&g_stats[2*b+0], sh1[0]);
        atomicAdd(&g_stats[2*b+1], sh2[0]);
    }
}

__global__ void finalize_kernel() {
    int b = threadIdx.x;
    if (b < Bz) {
        float n = (float)Tz * (float)Dz;
        float mean = g_stats[2*b] / n;
        float var  = g_stats[2*b+1] / n - mean*mean;
        g_mean[b] = mean;
        g_rstd[b] = rsqrtf(var + 1e-5f);
    }
}

// GroupNorm apply: g_att -> g_xr (tf32-rounded), ready for the W_o GEMM
__global__ void norm_kernel(const float* __restrict__ gamma, const float* __restrict__ beta)
{
    int idx = blockIdx.x * blockDim.x + threadIdx.x;
    long e = (long)idx * 4;
    if (e >= (long)BT*Dz) return;
    int d = (int)(e & (Dz-1));
    int b = (int)(e >> 21);             // e / (Tz*Dz)
    float mean = g_mean[b], rstd = g_rstd[b];

    float4 a = *(const float4*)(g_att + e);
    float4 gv = *(const float4*)(gamma + d);
    float4 bv = *(const float4*)(beta + d);
    float4 o;
    o.x = rtf((a.x - mean)*rstd*gv.x + bv.x);
    o.y = rtf((a.y - mean)*rstd*gv.y + bv.y);
    o.z = rtf((a.z - mean)*rstd*gv.z + bv.z);
    o.w = rtf((a.w - mean)*rstd*gv.w + bv.w);
    *(float4*)(g_xr + e) = o;
}

// ---------------- launcher ---------------------------------------------------
extern "C" void kernel_launch(void* const* d_in, const int* in_sizes, int n_in,
                              void* d_out, int out_size)
{
    const float* x      = (const float*)d_in[0];
    const float* state  = (const float*)d_in[1];
    const float* W_r    = (const float*)d_in[2];
    const float* W_k    = (const float*)d_in[3];
    const float* W_v    = (const float*)d_in[4];
    const float* W_o    = (const float*)d_in[5];
    const float* tmr    = (const float*)d_in[6];
    const float* tmk    = (const float*)d_in[7];
    const float* tmv    = (const float*)d_in[8];
    const float* tdecay = (const float*)d_in[9];
    const float* tfirst = (const float*)d_in[10];
    const float* gamma  = (const float*)d_in[11];
    const float* beta   = (const float*)d_in[12];
    float* out = (float*)d_out;

    float *p_xr, *p_xk, *p_xv, *p_r, *p_k, *p_v, *p_att, *p_W;
    cudaGetSymbolAddress((void**)&p_xr,  g_xr);
    cudaGetSymbolAddress((void**)&p_xk,  g_xk);
    cudaGetSymbolAddress((void**)&p_xv,  g_xv);
    cudaGetSymbolAddress((void**)&p_r,   g_r);
    cudaGetSymbolAddress((void**)&p_k,   g_k);
    cudaGetSymbolAddress((void**)&p_v,   g_v);
    cudaGetSymbolAddress((void**)&p_att, g_att);
    cudaGetSymbolAddress((void**)&p_W,   g_W);

    cudaFuncSetAttribute(gemm_mma<0>, cudaFuncAttributeMaxDynamicSharedMemorySize, GSMEM);
    cudaFuncSetAttribute(gemm_mma<1>, cudaFuncAttributeMaxDynamicSharedMemorySize, GSMEM);

    zero_stats_kernel<<<1, 32>>>();
    round_w_kernel<<<dim3(Dz*Dz/4/256, 4), 256>>>(W_r, W_k, W_v, W_o);
    mix_kernel<<<(BT*Dz/4 + 255)/256, 256>>>(x, state, tmr, tmk, tmv);

    dim3 ggrid(Dz/128, BT/128);   // (8, 128)
    gemm_mma<1><<<ggrid, 256, GSMEM>>>(p_xr, p_W + 0*(size_t)Dz*Dz, p_r);
    gemm_mma<0><<<ggrid, 256, GSMEM>>>(p_xk, p_W + 1*(size_t)Dz*Dz, p_k);
    gemm_mma<0><<<ggrid, 256, GSMEM>>>(p_xv, p_W + 2*(size_t)Dz*Dz, p_v);

    wkv_kernel<<<dim3(Kz/256, Bz), 256>>>(state, tdecay, tfirst);
    finalize_kernel<<<1, 32>>>();
    norm_kernel<<<(BT*Dz/4 + 255)/256, 256>>>(gamma, beta);

    gemm_mma<0><<<ggrid, 256, GSMEM>>>(p_xr, p_W + 3*(size_t)Dz*Dz, out);
}

// round 5
// speedup vs baseline: 5.7034x; 1.7385x over previous
#include <cuda_runtime.h>
#include <cstdint>

#define Bz 8
#define Tz 2048
#define Dz 1024
#define Kz 1024
#define BT (Bz*Tz)
#define NCH 8
#define LCH (Tz/NCH)     // 256

// ---------------- scratch (device globals; no allocations allowed) ----------
__device__ float g_xr[BT*Dz];
__device__ float g_xk[BT*Dz];
__device__ float g_xv[BT*Dz];
__device__ float g_r [BT*Dz];
__device__ float g_k [BT*Dz];
__device__ float g_v [BT*Dz];
__device__ float g_att[BT*Dz];
__device__ float g_W[4][Dz*Dz];          // tf32-rounded W_r,W_k,W_v,W_o
__device__ float g_chunk[Bz*NCH*Kz*2];
__device__ float g_init [Bz*NCH*Kz*2];
__device__ float g_stats[2*Bz];
__device__ float g_mean[Bz];
__device__ float g_rstd[Bz];

// ---------------- helpers ----------------------------------------------------
__device__ __forceinline__ float rtf(float x) {
    uint32_t r;
    asm("cvt.rna.tf32.f32 %0, %1;" : "=r"(r) : "f"(x));
    return __uint_as_float(r);
}
__device__ __forceinline__ void cp16(uint32_t saddr, const void* g) {
    asm volatile("cp.async.cg.shared.global [%0], [%1], 16;" :: "r"(saddr), "l"(g) : "memory");
}
#define CP_COMMIT() asm volatile("cp.async.commit_group;" ::: "memory")
#define CP_WAIT1()  asm volatile("cp.async.wait_group 1;" ::: "memory")
#define CP_WAIT0()  asm volatile("cp.async.wait_group 0;" ::: "memory")

__device__ __forceinline__ uint32_t smem_u32(const void* p) {
    uint32_t a;
    asm("{ .reg .u64 t; cvta.to.shared.u64 t, %1; cvt.u32.u64 %0, t; }" : "=r"(a) : "l"(p));
    return a;
}
__device__ __forceinline__ void mma_tf32(float* d, const uint32_t* a, const uint32_t* b) {
    asm volatile(
        "mma.sync.aligned.m16n8k8.row.col.f32.tf32.tf32.f32 "
        "{%0,%1,%2,%3}, {%4,%5,%6,%7}, {%8,%9}, {%0,%1,%2,%3};"
        : "+f"(d[0]), "+f"(d[1]), "+f"(d[2]), "+f"(d[3])
        : "r"(a[0]), "r"(a[1]), "r"(a[2]), "r"(a[3]), "r"(b[0]), "r"(b[1]));
}

// ---------------- small kernels ----------------------------------------------
__global__ void zero_stats_kernel() {
    int i = threadIdx.x;
    if (i < 2*Bz) g_stats[i] = 0.f;
}

__global__ void round_w_kernel(const float* __restrict__ w0, const float* __restrict__ w1,
                               const float* __restrict__ w2, const float* __restrict__ w3)
{
    int m = blockIdx.y;
    const float* s = (m == 0) ? w0 : (m == 1) ? w1 : (m == 2) ? w2 : w3;
    long e = ((long)blockIdx.x * blockDim.x + threadIdx.x) * 4;
    if (e >= (long)Dz*Dz) return;
    float4 v = *(const float4*)(s + e);
    v.x = rtf(v.x); v.y = rtf(v.y); v.z = rtf(v.z); v.w = rtf(v.w);
    *(float4*)(&g_W[m][0] + e) = v;
}

__global__ void mix_kernel(const float* __restrict__ x,
                           const float* __restrict__ state,
                           const float* __restrict__ tmr,
                           const float* __restrict__ tmk,
                           const float* __restrict__ tmv)
{
    int idx = blockIdx.x * blockDim.x + threadIdx.x;
    long e = (long)idx * 4;
    if (e >= (long)BT*Dz) return;
    int d  = (int)(e & (Dz-1));
    int bt = (int)(e >> 10);
    int t  = bt & (Tz-1);
    int b  = bt >> 11;

    float4 xc = *(const float4*)(x + e);
    float4 xp;
    if (t == 0) {
        xp.x = state[(b*Kz + d + 0)*3 + 2];
        xp.y = state[(b*Kz + d + 1)*3 + 2];
        xp.z = state[(b*Kz + d + 2)*3 + 2];
        xp.w = state[(b*Kz + d + 3)*3 + 2];
    } else {
        xp = *(const float4*)(x + e - Dz);
    }
    float4 mr = *(const float4*)(tmr + d);
    float4 mk = *(const float4*)(tmk + d);
    float4 mv = *(const float4*)(tmv + d);

    float4 o;
    o.x = rtf(xc.x*mr.x + xp.x*(1.f-mr.x));
    o.y = rtf(xc.y*mr.y + xp.y*(1.f-mr.y));
    o.z = rtf(xc.z*mr.z + xp.z*(1.f-mr.z));
    o.w = rtf(xc.w*mr.w + xp.w*(1.f-mr.w));
    *(float4*)(g_xr + e) = o;

    o.x = rtf(xc.x*mk.x + xp.x*(1.f-mk.x));
    o.y = rtf(xc.y*mk.y + xp.y*(1.f-mk.y));
    o.z = rtf(xc.z*mk.z + xp.z*(1.f-mk.z));
    o.w = rtf(xc.w*mk.w + xp.w*(1.f-mk.w));
    *(float4*)(g_xk + e) = o;

    o.x = rtf(xc.x*mv.x + xp.x*(1.f-mv.x));
    o.y = rtf(xc.y*mv.y + xp.y*(1.f-mv.y));
    o.z = rtf(xc.z*mv.z + xp.z*(1.f-mv.z));
    o.w = rtf(xc.w*mv.w + xp.w*(1.f-mv.w));
    *(float4*)(g_xv + e) = o;
}

// ---------------- TF32 mma.sync GEMM: C[M,N] = A[M,K] * W[N,K]^T -------------
// CTA tile 128x256, 8 warps (2x4), warp tile 64x64, BK=32, 3-stage cp.async.
#define BMt 128
#define BNt 256
#define BKg 32
#define STRIDEW 36
#define STG_A (BMt*STRIDEW)
#define STG_B (BNt*STRIDEW)
#define STG_TOT (STG_A+STG_B)
#define NSTAGE 3
#define GSMEM (NSTAGE*STG_TOT*4)        // 165888 bytes
#define NCHUNK (Dz/BKg)                 // 32

template<int MODE>
__global__ void __launch_bounds__(256)
gemm_mma(const float* __restrict__ A, const float* __restrict__ W, float* __restrict__ C)
{
    extern __shared__ float smf[];
    const int tid  = threadIdx.x;
    const int wid  = tid >> 5;
    const int lane = tid & 31;
    const int gp   = lane >> 2;
    const int tg   = lane & 3;
    const int wm   = (wid >> 2) * 64;
    const int wn   = (wid & 3) * 64;
    const int bm   = blockIdx.y * BMt;
    const int bn   = blockIdx.x * BNt;

    const float* Ag = A + (size_t)bm * Dz;
    const float* Wg = W + (size_t)bn * Dz;
    const uint32_t smb = smem_u32(smf);

    const int lrow = tid >> 3;   // 0..31
    const int lseg = tid & 7;    // 0..7

    auto issue = [&](int it) {
        int s = it % NSTAGE;
        uint32_t stA = smb + (uint32_t)s * STG_TOT * 4;
        uint32_t stB = stA + STG_A * 4;
        int k0 = it * BKg;
        #pragma unroll
        for (int i = 0; i < 4; i++) {
            int r = lrow + 32 * i;
            cp16(stA + (uint32_t)(r * STRIDEW + lseg * 4) * 4,
                 Ag + (size_t)r * Dz + k0 + lseg * 4);
        }
        #pragma unroll
        for (int i = 0; i < 8; i++) {
            int r = lrow + 32 * i;
            cp16(stB + (uint32_t)(r * STRIDEW + lseg * 4) * 4,
                 Wg + (size_t)r * Dz + k0 + lseg * 4);
        }
        CP_COMMIT();
    };

    float acc[4][8][4];
    #pragma unroll
    for (int mi = 0; mi < 4; mi++)
        #pragma unroll
        for (int ni = 0; ni < 8; ni++)
            #pragma unroll
            for (int q = 0; q < 4; q++) acc[mi][ni][q] = 0.f;

    issue(0);
    issue(1);

    #pragma unroll 1
    for (int it = 0; it < NCHUNK; it++) {
        int s = it % NSTAGE;
        CP_WAIT1();
        __syncthreads();
        if (it + 2 < NCHUNK) issue(it + 2);

        const float* stA = smf + s * STG_TOT;
        const float* stB = stA + STG_A;

        #pragma unroll
        for (int ks = 0; ks < 4; ks++) {
            uint32_t a[4][4], b[8][2];
            const int c = ks * 8 + tg;
            #pragma unroll
            for (int mi = 0; mi < 4; mi++) {
                int r = wm + mi * 16 + gp;
                a[mi][0] = __float_as_uint(stA[r * STRIDEW + c]);
                a[mi][1] = __float_as_uint(stA[(r + 8) * STRIDEW + c]);
                a[mi][2] = __float_as_uint(stA[r * STRIDEW + c + 4]);
                a[mi][3] = __float_as_uint(stA[(r + 8) * STRIDEW + c + 4]);
            }
            #pragma unroll
            for (int ni = 0; ni < 8; ni++) {
                int n = wn + ni * 8 + gp;
                b[ni][0] = __float_as_uint(stB[n * STRIDEW + c]);
                b[ni][1] = __float_as_uint(stB[n * STRIDEW + c + 4]);
            }
            #pragma unroll
            for (int mi = 0; mi < 4; mi++)
                #pragma unroll
                for (int ni = 0; ni < 8; ni++)
                    mma_tf32(acc[mi][ni], a[mi], b[ni]);
        }
    }
    CP_WAIT0();

    #pragma unroll
    for (int mi = 0; mi < 4; mi++) {
        int r0 = bm + wm + mi * 16 + gp;
        #pragma unroll
        for (int ni = 0; ni < 8; ni++) {
            int cc = bn + wn + ni * 8 + tg * 2;
            float v0 = acc[mi][ni][0], v1 = acc[mi][ni][1];
            float v2 = acc[mi][ni][2], v3 = acc[mi][ni][3];
            if (MODE == 1) {
                v0 = 1.f/(1.f+__expf(-v0));
                v1 = 1.f/(1.f+__expf(-v1));
                v2 = 1.f/(1.f+__expf(-v2));
                v3 = 1.f/(1.f+__expf(-v3));
            }
            *(float2*)(C + (size_t)r0 * Dz + cc)       = make_float2(v0, v1);
            *(float2*)(C + (size_t)(r0 + 8) * Dz + cc) = make_float2(v2, v3);
        }
    }
}

// ---------------- WKV chunked scan -------------------------------------------
// pass 1: per-chunk (num,den) reduction. grid (Kz/256, Bz, NCH)
__global__ void wkv_pass1(const float* __restrict__ tdecay)
{
    int b  = blockIdx.y;
    int ch = blockIdx.z;
    int c  = blockIdx.x * blockDim.x + threadIdx.x;

    float w = expf(-expf(tdecay[c]));
    size_t base = ((size_t)(b*Tz + ch*LCH))*Dz + c;
    const float* kp = g_k + base;
    const float* vp = g_v + base;

    float num = 0.f, den = 0.f;
    #pragma unroll 4
    for (int t = 0; t < LCH; t++) {
        float ek = __expf(kp[(size_t)t*Dz]);
        float vv = vp[(size_t)t*Dz];
        num = fmaf(ek, vv, num * w);
        den = fmaf(den, w, ek);
    }
    size_t idx = ((size_t)(b*NCH + ch)*Kz + c)*2;
    g_chunk[idx]   = num;
    g_chunk[idx+1] = den;
}

// pass 2: sequential combine of chunk states per channel (tiny)
__global__ void wkv_pass2(const float* __restrict__ state,
                          const float* __restrict__ tdecay)
{
    int gid = blockIdx.x * blockDim.x + threadIdx.x;
    if (gid >= Bz*Kz) return;
    int b = gid >> 10;
    int c = gid & (Kz-1);

    float ed = expf(tdecay[c]);
    float wL = expf(-ed * (float)LCH);    // w^LCH exactly

    float num = state[(b*Kz + c)*3 + 0];
    float den = state[(b*Kz + c)*3 + 1];
    #pragma unroll
    for (int ch = 0; ch < NCH; ch++) {
        size_t idx = ((size_t)(b*NCH + ch)*Kz + c)*2;
        g_init[idx]   = num;
        g_init[idx+1] = den;
        num = fmaf(num, wL, g_chunk[idx]);
        den = fmaf(den, wL, g_chunk[idx+1]);
    }
}

// pass 3: full scan within chunk from exact init; writes att + GN stats
__global__ void wkv_pass3(const float* __restrict__ tdecay,
                          const float* __restrict__ tfirst)
{
    int b  = blockIdx.y;
    int ch = blockIdx.z;
    int c  = blockIdx.x * blockDim.x + threadIdx.x;

    float w  = expf(-expf(tdecay[c]));
    float eu = expf(tfirst[c]);
    size_t idx = ((size_t)(b*NCH + ch)*Kz + c)*2;
    float num = g_init[idx];
    float den = g_init[idx+1];

    size_t base = ((size_t)(b*Tz + ch*LCH))*Dz + c;
    const float* kp = g_k   + base;
    const float* vp = g_v   + base;
    const float* rp = g_r   + base;
    float*       op = g_att + base;

    float s1 = 0.f, s2 = 0.f;
    #pragma unroll 4
    for (int t = 0; t < LCH; t++) {
        float kk = kp[(size_t)t*Dz];
        float vv = vp[(size_t)t*Dz];
        float rr = rp[(size_t)t*Dz];
        float ek = __expf(kk);
        float bonus = eu * ek;
        float wkv = __fdividef(fmaf(bonus, vv, num), den + bonus + 1e-9f);
        float att = rr * wkv;
        op[(size_t)t*Dz] = att;
        s1 += att;
        s2 = fmaf(att, att, s2);
        num = fmaf(ek, vv, num * w);
        den = fmaf(den, w, ek);
    }

    __shared__ float sh1[256], sh2[256];
    int tid = threadIdx.x;
    sh1[tid] = s1; sh2[tid] = s2;
    __syncthreads();
    for (int s = 128; s > 0; s >>= 1) {
        if (tid < s) { sh1[tid] += sh1[tid+s]; sh2[tid] += sh2[tid+s]; }
        __syncthreads();
    }
    if (tid == 0) {
        atomicAdd(&g_stats[2*b+0], sh1[0]);
        atomicAdd(&g_stats[2*b+1], sh2[0]);
    }
}

__global__ void finalize_kernel() {
    int b = threadIdx.x;
    if (b < Bz) {
        float n = (float)Tz * (float)Dz;
        float mean = g_stats[2*b] / n;
        float var  = g_stats[2*b+1] / n - mean*mean;
        g_mean[b] = mean;
        g_rstd[b] = rsqrtf(var + 1e-5f);
    }
}

// GroupNorm apply: g_att -> g_xr (tf32-rounded) for the W_o GEMM
__global__ void norm_kernel(const float* __restrict__ gamma, const float* __restrict__ beta)
{
    int idx = blockIdx.x * blockDim.x + threadIdx.x;
    long e = (long)idx * 4;
    if (e >= (long)BT*Dz) return;
    int d = (int)(e & (Dz-1));
    int b = (int)(e >> 21);
    float mean = g_mean[b], rstd = g_rstd[b];

    float4 a  = *(const float4*)(g_att + e);
    float4 gv = *(const float4*)(gamma + d);
    float4 bv = *(const float4*)(beta + d);
    float4 o;
    o.x = rtf((a.x - mean)*rstd*gv.x + bv.x);
    o.y = rtf((a.y - mean)*rstd*gv.y + bv.y);
    o.z = rtf((a.z - mean)*rstd*gv.z + bv.z);
    o.w = rtf((a.w - mean)*rstd*gv.w + bv.w);
    *(float4*)(g_xr + e) = o;
}

// ---------------- launcher ---------------------------------------------------
extern "C" void kernel_launch(void* const* d_in, const int* in_sizes, int n_in,
                              void* d_out, int out_size)
{
    const float* x      = (const float*)d_in[0];
    const float* state  = (const float*)d_in[1];
    const float* W_r    = (const float*)d_in[2];
    const float* W_k    = (const float*)d_in[3];
    const float* W_v    = (const float*)d_in[4];
    const float* W_o    = (const float*)d_in[5];
    const float* tmr    = (const float*)d_in[6];
    const float* tmk    = (const float*)d_in[7];
    const float* tmv    = (const float*)d_in[8];
    const float* tdecay = (const float*)d_in[9];
    const float* tfirst = (const float*)d_in[10];
    const float* gamma  = (const float*)d_in[11];
    const float* beta   = (const float*)d_in[12];
    float* out = (float*)d_out;

    float *p_xr, *p_xk, *p_xv, *p_r, *p_k, *p_v, *p_W;
    cudaGetSymbolAddress((void**)&p_xr,  g_xr);
    cudaGetSymbolAddress((void**)&p_xk,  g_xk);
    cudaGetSymbolAddress((void**)&p_xv,  g_xv);
    cudaGetSymbolAddress((void**)&p_r,   g_r);
    cudaGetSymbolAddress((void**)&p_k,   g_k);
    cudaGetSymbolAddress((void**)&p_v,   g_v);
    cudaGetSymbolAddress((void**)&p_W,   g_W);

    cudaFuncSetAttribute(gemm_mma<0>, cudaFuncAttributeMaxDynamicSharedMemorySize, GSMEM);
    cudaFuncSetAttribute(gemm_mma<1>, cudaFuncAttributeMaxDynamicSharedMemorySize, GSMEM);

    zero_stats_kernel<<<1, 32>>>();
    round_w_kernel<<<dim3(Dz*Dz/4/256, 4), 256>>>(W_r, W_k, W_v, W_o);
    mix_kernel<<<(BT*Dz/4 + 255)/256, 256>>>(x, state, tmr, tmk, tmv);

    dim3 ggrid(Dz/BNt, BT/BMt);   // (4, 128)
    gemm_mma<1><<<ggrid, 256, GSMEM>>>(p_xr, p_W + 0*(size_t)Dz*Dz, p_r);
    gemm_mma<0><<<ggrid, 256, GSMEM>>>(p_xk, p_W + 1*(size_t)Dz*Dz, p_k);
    gemm_mma<0><<<ggrid, 256, GSMEM>>>(p_xv, p_W + 2*(size_t)Dz*Dz, p_v);

    wkv_pass1<<<dim3(Kz/256, Bz, NCH), 256>>>(tdecay);
    wkv_pass2<<<Bz*Kz/256, 256>>>(state, tdecay);
    wkv_pass3<<<dim3(Kz/256, Bz, NCH), 256>>>(tdecay, tfirst);

    finalize_kernel<<<1, 32>>>();
    norm_kernel<<<(BT*Dz/4 + 255)/256, 256>>>(gamma, beta);

    gemm_mma<0><<<ggrid, 256, GSMEM>>>(p_xr, p_W + 3*(size_t)Dz*Dz, out);
}

// round 6
// speedup vs baseline: 6.5490x; 1.1483x over previous
#include <cuda_runtime.h>
#include <cstdint>

#define Bz 8
#define Tz 2048
#define Dz 1024
#define Kz 1024
#define BT (Bz*Tz)
#define NCH 8
#define LCH (Tz/NCH)     // 256

// ---------------- scratch (device globals; no allocations allowed) ----------
__device__ float g_xr[BT*Dz];
__device__ float g_xk[BT*Dz];
__device__ float g_xv[BT*Dz];
__device__ float g_r [BT*Dz];
__device__ float g_k [BT*Dz];
__device__ float g_v [BT*Dz];
__device__ float g_att[BT*Dz];
__device__ float g_W[4][Dz*Dz];          // tf32-rounded W_r,W_k,W_v,W_o
__device__ float g_chunk[Bz*NCH*Kz*2];
__device__ float g_init [Bz*NCH*Kz*2];
__device__ float g_stats[2*Bz];
__device__ float g_mean[Bz];
__device__ float g_rstd[Bz];

// ---------------- helpers ----------------------------------------------------
__device__ __forceinline__ float rtf(float x) {
    uint32_t r;
    asm("cvt.rna.tf32.f32 %0, %1;" : "=r"(r) : "f"(x));
    return __uint_as_float(r);
}
__device__ __forceinline__ void cp16(uint32_t saddr, const void* g) {
    asm volatile("cp.async.cg.shared.global [%0], [%1], 16;" :: "r"(saddr), "l"(g) : "memory");
}
#define CP_COMMIT() asm volatile("cp.async.commit_group;" ::: "memory")
#define CP_WAIT1()  asm volatile("cp.async.wait_group 1;" ::: "memory")
#define CP_WAIT0()  asm volatile("cp.async.wait_group 0;" ::: "memory")

__device__ __forceinline__ uint32_t smem_u32(const void* p) {
    uint32_t a;
    asm("{ .reg .u64 t; cvta.to.shared.u64 t, %1; cvt.u32.u64 %0, t; }" : "=r"(a) : "l"(p));
    return a;
}
__device__ __forceinline__ void mma_tf32(float* d, const uint32_t* a, const uint32_t* b) {
    asm volatile(
        "mma.sync.aligned.m16n8k8.row.col.f32.tf32.tf32.f32 "
        "{%0,%1,%2,%3}, {%4,%5,%6,%7}, {%8,%9}, {%0,%1,%2,%3};"
        : "+f"(d[0]), "+f"(d[1]), "+f"(d[2]), "+f"(d[3])
        : "r"(a[0]), "r"(a[1]), "r"(a[2]), "r"(a[3]), "r"(b[0]), "r"(b[1]));
}

// ---------------- small kernels ----------------------------------------------
__global__ void zero_stats_kernel() {
    int i = threadIdx.x;
    if (i < 2*Bz) g_stats[i] = 0.f;
}

__global__ void round_w_kernel(const float* __restrict__ w0, const float* __restrict__ w1,
                               const float* __restrict__ w2, const float* __restrict__ w3)
{
    int m = blockIdx.y;
    const float* s = (m == 0) ? w0 : (m == 1) ? w1 : (m == 2) ? w2 : w3;
    long e = ((long)blockIdx.x * blockDim.x + threadIdx.x) * 4;
    if (e >= (long)Dz*Dz) return;
    float4 v = *(const float4*)(s + e);
    v.x = rtf(v.x); v.y = rtf(v.y); v.z = rtf(v.z); v.w = rtf(v.w);
    *(float4*)(&g_W[m][0] + e) = v;
}

__global__ void mix_kernel(const float* __restrict__ x,
                           const float* __restrict__ state,
                           const float* __restrict__ tmr,
                           const float* __restrict__ tmk,
                           const float* __restrict__ tmv)
{
    int idx = blockIdx.x * blockDim.x + threadIdx.x;
    long e = (long)idx * 4;
    if (e >= (long)BT*Dz) return;
    int d  = (int)(e & (Dz-1));
    int bt = (int)(e >> 10);
    int t  = bt & (Tz-1);
    int b  = bt >> 11;

    float4 xc = *(const float4*)(x + e);
    float4 xp;
    if (t == 0) {
        xp.x = state[(b*Kz + d + 0)*3 + 2];
        xp.y = state[(b*Kz + d + 1)*3 + 2];
        xp.z = state[(b*Kz + d + 2)*3 + 2];
        xp.w = state[(b*Kz + d + 3)*3 + 2];
    } else {
        xp = *(const float4*)(x + e - Dz);
    }
    float4 mr = *(const float4*)(tmr + d);
    float4 mk = *(const float4*)(tmk + d);
    float4 mv = *(const float4*)(tmv + d);

    float4 o;
    o.x = rtf(xc.x*mr.x + xp.x*(1.f-mr.x));
    o.y = rtf(xc.y*mr.y + xp.y*(1.f-mr.y));
    o.z = rtf(xc.z*mr.z + xp.z*(1.f-mr.z));
    o.w = rtf(xc.w*mr.w + xp.w*(1.f-mr.w));
    *(float4*)(g_xr + e) = o;

    o.x = rtf(xc.x*mk.x + xp.x*(1.f-mk.x));
    o.y = rtf(xc.y*mk.y + xp.y*(1.f-mk.y));
    o.z = rtf(xc.z*mk.z + xp.z*(1.f-mk.z));
    o.w = rtf(xc.w*mk.w + xp.w*(1.f-mk.w));
    *(float4*)(g_xk + e) = o;

    o.x = rtf(xc.x*mv.x + xp.x*(1.f-mv.x));
    o.y = rtf(xc.y*mv.y + xp.y*(1.f-mv.y));
    o.z = rtf(xc.z*mv.z + xp.z*(1.f-mv.z));
    o.w = rtf(xc.w*mv.w + xp.w*(1.f-mv.w));
    *(float4*)(g_xv + e) = o;
}

// ---------------- TF32 mma.sync GEMM: C[M,N] = A[M,K] * W[N,K]^T -------------
// CTA tile 128x128, 4 warps (2x2), warp tile 64x64, BK=32, 2-stage cp.async.
// 3 CTAs/SM (regs 164*384=63K, smem 3*73.7KB=221KB).
#define BMt 128
#define BNt 128
#define BKg 32
#define STRIDEW 36
#define STG_A (BMt*STRIDEW)
#define STG_B (BNt*STRIDEW)
#define STG_TOT (STG_A+STG_B)
#define NSTAGE 2
#define GSMEM (NSTAGE*STG_TOT*4)        // 73728 bytes
#define NCHUNK (Dz/BKg)                 // 32

template<int MODE>
__global__ void __launch_bounds__(128, 3)
gemm_mma(const float* __restrict__ A, const float* __restrict__ W, float* __restrict__ C)
{
    extern __shared__ float smf[];
    const int tid  = threadIdx.x;
    const int wid  = tid >> 5;
    const int lane = tid & 31;
    const int gp   = lane >> 2;
    const int tg   = lane & 3;
    const int wm   = (wid >> 1) * 64;
    const int wn   = (wid & 1) * 64;
    const int bm   = blockIdx.y * BMt;
    const int bn   = blockIdx.x * BNt;

    const float* Ag = A + (size_t)bm * Dz;
    const float* Wg = W + (size_t)bn * Dz;
    const uint32_t smb = smem_u32(smf);

    const int lrow = tid >> 3;   // 0..15
    const int lseg = tid & 7;    // 0..7

    auto issue = [&](int it) {
        int s = it & 1;
        uint32_t stA = smb + (uint32_t)s * STG_TOT * 4;
        uint32_t stB = stA + STG_A * 4;
        int k0 = it * BKg;
        #pragma unroll
        for (int i = 0; i < 8; i++) {
            int r = lrow + 16 * i;
            cp16(stA + (uint32_t)(r * STRIDEW + lseg * 4) * 4,
                 Ag + (size_t)r * Dz + k0 + lseg * 4);
        }
        #pragma unroll
        for (int i = 0; i < 8; i++) {
            int r = lrow + 16 * i;
            cp16(stB + (uint32_t)(r * STRIDEW + lseg * 4) * 4,
                 Wg + (size_t)r * Dz + k0 + lseg * 4);
        }
        CP_COMMIT();
    };

    float acc[4][8][4];
    #pragma unroll
    for (int mi = 0; mi < 4; mi++)
        #pragma unroll
        for (int ni = 0; ni < 8; ni++)
            #pragma unroll
            for (int q = 0; q < 4; q++) acc[mi][ni][q] = 0.f;

    issue(0);
    issue(1);

    #pragma unroll 1
    for (int it = 0; it < NCHUNK; it++) {
        if (it == NCHUNK - 1) { CP_WAIT0(); } else { CP_WAIT1(); }
        __syncthreads();

        const float* stA = smf + (it & 1) * STG_TOT;
        const float* stB = stA + STG_A;

        #pragma unroll
        for (int ks = 0; ks < 4; ks++) {
            uint32_t a[4][4], b[8][2];
            const int c = ks * 8 + tg;
            #pragma unroll
            for (int mi = 0; mi < 4; mi++) {
                int r = wm + mi * 16 + gp;
                a[mi][0] = __float_as_uint(stA[r * STRIDEW + c]);
                a[mi][1] = __float_as_uint(stA[(r + 8) * STRIDEW + c]);
                a[mi][2] = __float_as_uint(stA[r * STRIDEW + c + 4]);
                a[mi][3] = __float_as_uint(stA[(r + 8) * STRIDEW + c + 4]);
            }
            #pragma unroll
            for (int ni = 0; ni < 8; ni++) {
                int n = wn + ni * 8 + gp;
                b[ni][0] = __float_as_uint(stB[n * STRIDEW + c]);
                b[ni][1] = __float_as_uint(stB[n * STRIDEW + c + 4]);
            }
            #pragma unroll
            for (int mi = 0; mi < 4; mi++)
                #pragma unroll
                for (int ni = 0; ni < 8; ni++)
                    mma_tf32(acc[mi][ni], a[mi], b[ni]);
        }
        __syncthreads();
        if (it + 2 < NCHUNK) issue(it + 2);
    }

    #pragma unroll
    for (int mi = 0; mi < 4; mi++) {
        int r0 = bm + wm + mi * 16 + gp;
        #pragma unroll
        for (int ni = 0; ni < 8; ni++) {
            int cc = bn + wn + ni * 8 + tg * 2;
            float v0 = acc[mi][ni][0], v1 = acc[mi][ni][1];
            float v2 = acc[mi][ni][2], v3 = acc[mi][ni][3];
            if (MODE == 1) {
                v0 = 1.f/(1.f+__expf(-v0));
                v1 = 1.f/(1.f+__expf(-v1));
                v2 = 1.f/(1.f+__expf(-v2));
                v3 = 1.f/(1.f+__expf(-v3));
            }
            *(float2*)(C + (size_t)r0 * Dz + cc)       = make_float2(v0, v1);
            *(float2*)(C + (size_t)(r0 + 8) * Dz + cc) = make_float2(v2, v3);
        }
    }
}

// ---------------- WKV chunked scan -------------------------------------------
__global__ void wkv_pass1(const float* __restrict__ tdecay)
{
    int b  = blockIdx.y;
    int ch = blockIdx.z;
    int c  = blockIdx.x * blockDim.x + threadIdx.x;

    float w = expf(-expf(tdecay[c]));
    size_t base = ((size_t)(b*Tz + ch*LCH))*Dz + c;
    const float* kp = g_k + base;
    const float* vp = g_v + base;

    float num = 0.f, den = 0.f;
    #pragma unroll 4
    for (int t = 0; t < LCH; t++) {
        float ek = __expf(kp[(size_t)t*Dz]);
        float vv = vp[(size_t)t*Dz];
        num = fmaf(ek, vv, num * w);
        den = fmaf(den, w, ek);
    }
    size_t idx = ((size_t)(b*NCH + ch)*Kz + c)*2;
    g_chunk[idx]   = num;
    g_chunk[idx+1] = den;
}

__global__ void wkv_pass2(const float* __restrict__ state,
                          const float* __restrict__ tdecay)
{
    int gid = blockIdx.x * blockDim.x + threadIdx.x;
    if (gid >= Bz*Kz) return;
    int b = gid >> 10;
    int c = gid & (Kz-1);

    float ed = expf(tdecay[c]);
    float wL = expf(-ed * (float)LCH);    // w^LCH exactly

    float num = state[(b*Kz + c)*3 + 0];
    float den = state[(b*Kz + c)*3 + 1];
    #pragma unroll
    for (int ch = 0; ch < NCH; ch++) {
        size_t idx = ((size_t)(b*NCH + ch)*Kz + c)*2;
        g_init[idx]   = num;
        g_init[idx+1] = den;
        num = fmaf(num, wL, g_chunk[idx]);
        den = fmaf(den, wL, g_chunk[idx+1]);
    }
}

__global__ void wkv_pass3(const float* __restrict__ tdecay,
                          const float* __restrict__ tfirst)
{
    int b  = blockIdx.y;
    int ch = blockIdx.z;
    int c  = blockIdx.x * blockDim.x + threadIdx.x;

    float w  = expf(-expf(tdecay[c]));
    float eu = expf(tfirst[c]);
    size_t idx = ((size_t)(b*NCH + ch)*Kz + c)*2;
    float num = g_init[idx];
    float den = g_init[idx+1];

    size_t base = ((size_t)(b*Tz + ch*LCH))*Dz + c;
    const float* kp = g_k   + base;
    const float* vp = g_v   + base;
    const float* rp = g_r   + base;
    float*       op = g_att + base;

    float s1 = 0.f, s2 = 0.f;
    #pragma unroll 4
    for (int t = 0; t < LCH; t++) {
        float kk = kp[(size_t)t*Dz];
        float vv = vp[(size_t)t*Dz];
        float rr = rp[(size_t)t*Dz];
        float ek = __expf(kk);
        float bonus = eu * ek;
        float wkv = __fdividef(fmaf(bonus, vv, num), den + bonus + 1e-9f);
        float att = rr * wkv;
        op[(size_t)t*Dz] = att;
        s1 += att;
        s2 = fmaf(att, att, s2);
        num = fmaf(ek, vv, num * w);
        den = fmaf(den, w, ek);
    }

    __shared__ float sh1[256], sh2[256];
    int tid = threadIdx.x;
    sh1[tid] = s1; sh2[tid] = s2;
    __syncthreads();
    for (int s = 128; s > 0; s >>= 1) {
        if (tid < s) { sh1[tid] += sh1[tid+s]; sh2[tid] += sh2[tid+s]; }
        __syncthreads();
    }
    if (tid == 0) {
        atomicAdd(&g_stats[2*b+0], sh1[0]);
        atomicAdd(&g_stats[2*b+1], sh2[0]);
    }
}

__global__ void finalize_kernel() {
    int b = threadIdx.x;
    if (b < Bz) {
        float n = (float)Tz * (float)Dz;
        float mean = g_stats[2*b] / n;
        float var  = g_stats[2*b+1] / n - mean*mean;
        g_mean[b] = mean;
        g_rstd[b] = rsqrtf(var + 1e-5f);
    }
}

__global__ void norm_kernel(const float* __restrict__ gamma, const float* __restrict__ beta)
{
    int idx = blockIdx.x * blockDim.x + threadIdx.x;
    long e = (long)idx * 4;
    if (e >= (long)BT*Dz) return;
    int d = (int)(e & (Dz-1));
    int b = (int)(e >> 21);
    float mean = g_mean[b], rstd = g_rstd[b];

    float4 a  = *(const float4*)(g_att + e);
    float4 gv = *(const float4*)(gamma + d);
    float4 bv = *(const float4*)(beta + d);
    float4 o;
    o.x = rtf((a.x - mean)*rstd*gv.x + bv.x);
    o.y = rtf((a.y - mean)*rstd*gv.y + bv.y);
    o.z = rtf((a.z - mean)*rstd*gv.z + bv.z);
    o.w = rtf((a.w - mean)*rstd*gv.w + bv.w);
    *(float4*)(g_xr + e) = o;
}

// ---------------- launcher ---------------------------------------------------
extern "C" void kernel_launch(void* const* d_in, const int* in_sizes, int n_in,
                              void* d_out, int out_size)
{
    const float* x      = (const float*)d_in[0];
    const float* state  = (const float*)d_in[1];
    const float* W_r    = (const float*)d_in[2];
    const float* W_k    = (const float*)d_in[3];
    const float* W_v    = (const float*)d_in[4];
    const float* W_o    = (const float*)d_in[5];
    const float* tmr    = (const float*)d_in[6];
    const float* tmk    = (const float*)d_in[7];
    const float* tmv    = (const float*)d_in[8];
    const float* tdecay = (const float*)d_in[9];
    const float* tfirst = (const float*)d_in[10];
    const float* gamma  = (const float*)d_in[11];
    const float* beta   = (const float*)d_in[12];
    float* out = (float*)d_out;

    float *p_xr, *p_xk, *p_xv, *p_r, *p_k, *p_v, *p_W;
    cudaGetSymbolAddress((void**)&p_xr,  g_xr);
    cudaGetSymbolAddress((void**)&p_xk,  g_xk);
    cudaGetSymbolAddress((void**)&p_xv,  g_xv);
    cudaGetSymbolAddress((void**)&p_r,   g_r);
    cudaGetSymbolAddress((void**)&p_k,   g_k);
    cudaGetSymbolAddress((void**)&p_v,   g_v);
    cudaGetSymbolAddress((void**)&p_W,   g_W);

    cudaFuncSetAttribute(gemm_mma<0>, cudaFuncAttributeMaxDynamicSharedMemorySize, GSMEM);
    cudaFuncSetAttribute(gemm_mma<1>, cudaFuncAttributeMaxDynamicSharedMemorySize, GSMEM);

    zero_stats_kernel<<<1, 32>>>();
    round_w_kernel<<<dim3(Dz*Dz/4/256, 4), 256>>>(W_r, W_k, W_v, W_o);
    mix_kernel<<<(BT*Dz/4 + 255)/256, 256>>>(x, state, tmr, tmk, tmv);

    dim3 ggrid(Dz/BNt, BT/BMt);   // (8, 128)
    gemm_mma<1><<<ggrid, 128, GSMEM>>>(p_xr, p_W + 0*(size_t)Dz*Dz, p_r);
    gemm_mma<0><<<ggrid, 128, GSMEM>>>(p_xk, p_W + 1*(size_t)Dz*Dz, p_k);
    gemm_mma<0><<<ggrid, 128, GSMEM>>>(p_xv, p_W + 2*(size_t)Dz*Dz, p_v);

    wkv_pass1<<<dim3(Kz/256, Bz, NCH), 256>>>(tdecay);
    wkv_pass2<<<Bz*Kz/256, 256>>>(state, tdecay);
    wkv_pass3<<<dim3(Kz/256, Bz, NCH), 256>>>(tdecay, tfirst);

    finalize_kernel<<<1, 32>>>();
    norm_kernel<<<(BT*Dz/4 + 255)/256, 256>>>(gamma, beta);

    gemm_mma<0><<<ggrid, 128, GSMEM>>>(p_xr, p_W + 3*(size_t)Dz*Dz, out);
}